// round 14
// baseline (speedup 1.0000x reference)
#include <cuda_runtime.h>
#include <cuda_bf16.h>
#include <cstdint>
#include <cstddef>

#define N_USERS   100000
#define N_NODES   500000
#define DIM       64
#define N_EDGES   2000000
#define BATCH     4096
#define NWORDS    ((N_NODES + 31) / 32)

// -------- device scratch (static, allocation-free) --------
// NOTE: never touch these symbols from host code (GB300 ATS would silently
// route through the host shadow at 200GB/s). All access via device selectors.
__device__ __nv_bfloat16 g_EB[(size_t)N_NODES * DIM];  // bf16 copy of emb
__device__ __nv_bfloat16 g_XA[(size_t)N_NODES * DIM];  // bf16 layer buffers
__device__ __nv_bfloat16 g_XB[(size_t)N_NODES * DIM];
__device__ __nv_bfloat16 g_XC[(size_t)N_NODES * DIM];
__device__ float    g_dinv[N_NODES];
__device__ unsigned g_deg[N_NODES];
__device__ unsigned g_fb[3][NWORDS];       // needed-node bitmasks (L2-resident)
__device__ int      g_nl[3][N_NODES];      // compact node lists
__device__ int      g_ncnt[3];
__device__ int2     g_le[3][N_EDGES];      // compact edge lists (src,dst)
__device__ int      g_ecnt[3];

__device__ __forceinline__ __nv_bfloat16* xbuf(int sel) {
    return sel == 0 ? g_EB : (sel == 1 ? g_XA : (sel == 2 ? g_XB : g_XC));
}

// -------- init counters + flag bitmasks --------
__global__ void k_init() {
    int i = blockIdx.x * blockDim.x + threadIdx.x;
    if (i < N_NODES) g_deg[i] = 0u;
    if (i < NWORDS) { g_fb[0][i] = 0u; g_fb[1][i] = 0u; g_fb[2][i] = 0u; }
    if (i < 3) { g_ncnt[i] = 0; g_ecnt[i] = 0; }
}

__global__ void k_dinv() {
    int i = blockIdx.x * blockDim.x + threadIdx.x;
    if (i < N_NODES) {
        unsigned d = g_deg[i];
        g_dinv[i] = d ? rsqrtf((float)d) : 0.0f;
    }
}

// convert emb (fp32) -> g_EB (bf16); one thread per 8 floats
__global__ void k_conv(const float* __restrict__ emb) {
    int t = blockIdx.x * blockDim.x + threadIdx.x;
    if (t >= N_NODES * (DIM / 8)) return;
    float4 a = __ldg((const float4*)emb + 2 * (size_t)t);
    float4 b = __ldg((const float4*)emb + 2 * (size_t)t + 1);
    __nv_bfloat162 p0 = __float22bfloat162_rn(make_float2(a.x, a.y));
    __nv_bfloat162 p1 = __float22bfloat162_rn(make_float2(a.z, a.w));
    __nv_bfloat162 p2 = __float22bfloat162_rn(make_float2(b.x, b.y));
    __nv_bfloat162 p3 = __float22bfloat162_rn(make_float2(b.z, b.w));
    uint4 o;
    o.x = *(unsigned*)&p0; o.y = *(unsigned*)&p1;
    o.z = *(unsigned*)&p2; o.w = *(unsigned*)&p3;
    ((uint4*)g_EB)[t] = o;
}

// warp-aggregated single-item append
__device__ __forceinline__ int wagg_append(int* counter, bool pred) {
    unsigned mask = __ballot_sync(0xffffffffu, pred);
    if (!pred) return -1;
    int lane   = threadIdx.x & 31;
    int leader = __ffs(mask) - 1;
    int rank   = __popc(mask & ((1u << lane) - 1));
    int base = 0;
    if (lane == leader) base = atomicAdd(counter, __popc(mask));
    base = __shfl_sync(mask, base, leader);
    return base + rank;
}

// warp-scan multi-append: ONE atomic per warp; all lanes participate
__device__ __forceinline__ int wscan_append(int* counter, int cnt) {
    int lane = threadIdx.x & 31;
    int incl = cnt;
#pragma unroll
    for (int o = 1; o < 32; o <<= 1) {
        int v = __shfl_up_sync(0xffffffffu, incl, o);
        if (lane >= o) incl += v;
    }
    int total = __shfl_sync(0xffffffffu, incl, 31);
    int base = 0;
    if (lane == 31 && total) base = atomicAdd(counter, total);
    base = __shfl_sync(0xffffffffu, base, 31);
    return base + incl - cnt;
}

__device__ __forceinline__ bool mark_node(int L, int idx) {
    unsigned bit = 1u << (idx & 31);
    unsigned old = atomicOr(&g_fb[L][idx >> 5], bit);
    return (old & bit) == 0u;
}

__device__ __forceinline__ bool test_node(int L, int idx) {
    return (g_fb[L][idx >> 5] >> (idx & 31)) & 1u;
}

// mark batch nodes in all 3 bitmasks + node lists; also zero the output scalar
__global__ void k_mark_batch(const int* __restrict__ u,
                             const int* __restrict__ p,
                             const int* __restrict__ n,
                             float* __restrict__ out) {
    int t = blockIdx.x * blockDim.x + threadIdx.x;
    if (t == 0) out[0] = 0.0f;
    bool act = (t < 9 * BATCH);
    int L = 0, idx = 0;
    if (act) {
        L = t / (3 * BATCH);
        int r = t - L * (3 * BATCH);
        idx = (r < BATCH) ? u[r]
            : (r < 2 * BATCH) ? p[r - BATCH]
                              : n[r - 2 * BATCH];
        act = mark_node(L, idx);
    }
#pragma unroll
    for (int LL = 0; LL < 3; LL++) {
        bool pred = act && (L == LL);
        int slot = wagg_append(&g_ncnt[LL], pred);
        if (pred) g_nl[LL][slot] = idx;
    }
}

// compaction, 8 edges/thread, warp-scan appends.
// pass: f[gate][dst] && (excl < 0 || !f[excl][dst]); optionally mark prev.
// do_deg: also accumulate in-degree for all 8 dsts (fused former k_deg).
__global__ void k_compact8s(const int* __restrict__ src, const int* __restrict__ dst,
                            int gate, int excl, int prev, int has_prev, int do_deg) {
    int t = blockIdx.x * blockDim.x + threadIdx.x;
    bool inb = (t < N_EDGES / 8);
    int4 dA = make_int4(0,0,0,0), dB = make_int4(0,0,0,0);
    if (inb) {
        dA = __ldg((const int4*)dst + 2 * t);
        dB = __ldg((const int4*)dst + 2 * t + 1);
    }
    int dd[8] = {dA.x, dA.y, dA.z, dA.w, dB.x, dB.y, dB.z, dB.w};

    if (do_deg && inb) {
#pragma unroll
        for (int i = 0; i < 8; i++)
            atomicAdd(&g_deg[dd[i]], 1u);
    }

    bool p[8];
    int cnt = 0;
#pragma unroll
    for (int i = 0; i < 8; i++) {
        p[i] = inb && test_node(gate, dd[i]);
        if (excl >= 0 && p[i]) p[i] = !test_node(excl, dd[i]);
        cnt += p[i];
    }
    int4 sA = make_int4(0,0,0,0), sB = make_int4(0,0,0,0);
    if (cnt) {
        sA = __ldg((const int4*)src + 2 * t);
        sB = __ldg((const int4*)src + 2 * t + 1);
    }
    int ss[8] = {sA.x, sA.y, sA.z, sA.w, sB.x, sB.y, sB.z, sB.w};

    int off = wscan_append(&g_ecnt[gate], cnt);
#pragma unroll
    for (int i = 0; i < 8; i++)
        if (p[i]) g_le[gate][off++] = make_int2(ss[i], dd[i]);

    if (has_prev) {
        bool nw[8];
        int ncnt = 0;
#pragma unroll
        for (int i = 0; i < 8; i++) {
            nw[i] = p[i] && mark_node(prev, ss[i]);
            ncnt += nw[i];
        }
        int noff = wscan_append(&g_ncnt[prev], ncnt);
#pragma unroll
        for (int i = 0; i < 8; i++)
            if (nw[i]) g_nl[prev][noff++] = ss[i];
    }
}

// zero all three bf16 buffers over their node lists in ONE kernel.
// 128B rows = 8 x uint4 per row.
__global__ void k_zero_all() {
    int n0 = g_ncnt[0] * 8, n1 = g_ncnt[1] * 8, n2 = g_ncnt[2] * 8;
    int ntot = n0 + n1 + n2;
    int stride = gridDim.x * blockDim.x;
    for (int t = blockIdx.x * blockDim.x + threadIdx.x; t < ntot; t += stride) {
        uint4* y;
        int r, c;
        if (t < n0)            { y = (uint4*)g_XA; r = g_nl[0][t >> 3];        c = t & 7; }
        else if (t < n0 + n1)  { int q = t - n0;
                                 y = (uint4*)g_XB; r = g_nl[1][q >> 3];        c = q & 7; }
        else                   { int q = t - n0 - n1;
                                 y = (uint4*)g_XC; r = g_nl[2][q >> 3];        c = q & 7; }
        y[(size_t)r * 8 + c] = make_uint4(0u, 0u, 0u, 0u);
    }
}

// bf16 propagation over compact edge list: 8 lanes/edge, grid-stride.
__global__ void k_prop_list(int xsel, int ysel, int lsel) {
    int m = g_ecnt[lsel] * 8;
    const uint4* x = (const uint4*)xbuf(xsel);
    uint4*       y = (uint4*)xbuf(ysel);
    int stride = gridDim.x * blockDim.x;
    for (int t = blockIdx.x * blockDim.x + threadIdx.x; t < m; t += stride) {
        int e = t >> 3, lane = t & 7;
        int2  sd = __ldg(&g_le[lsel][e]);
        float w = __ldg(g_dinv + sd.x) * __ldg(g_dinv + sd.y);
        __nv_bfloat162 w2 = __float2bfloat162_rn(w);
        uint4 v = __ldg(x + (size_t)sd.x * 8 + lane);
        __nv_bfloat162 q0 = __hmul2(*(__nv_bfloat162*)&v.x, w2);
        __nv_bfloat162 q1 = __hmul2(*(__nv_bfloat162*)&v.y, w2);
        __nv_bfloat162 q2 = __hmul2(*(__nv_bfloat162*)&v.z, w2);
        __nv_bfloat162 q3 = __hmul2(*(__nv_bfloat162*)&v.w, w2);
        uint4* a = y + (size_t)sd.y * 8 + lane;
        asm volatile("red.global.add.noftz.v4.bf16x2 [%0], {%1, %2, %3, %4};"
                     :: "l"(a), "r"(*(unsigned*)&q0), "r"(*(unsigned*)&q1),
                        "r"(*(unsigned*)&q2), "r"(*(unsigned*)&q3)
                     : "memory");
    }
}

// -------- fused final loss: one warp per batch element --------
__global__ void k_loss(const float* __restrict__ emb,
                       const int* __restrict__ user,
                       const int* __restrict__ pos,
                       const int* __restrict__ neg,
                       float* __restrict__ out) {
    int w = (blockIdx.x * blockDim.x + threadIdx.x) >> 5;
    int lane = threadIdx.x & 31;
    if (w >= BATCH) return;

    int ui = user[w], pi = pos[w], ni = neg[w];

    const float2* E = (const float2*)emb;
    const __nv_bfloat162* A = (const __nv_bfloat162*)g_XA;
    const __nv_bfloat162* B = (const __nv_bfloat162*)g_XB;
    const __nv_bfloat162* C = (const __nv_bfloat162*)g_XC;

    size_t uo = (size_t)ui * 32 + lane;
    size_t po = (size_t)pi * 32 + lane;
    size_t no = (size_t)ni * 32 + lane;

    float2 eu = __ldg(E + uo), ep = __ldg(E + po), en = __ldg(E + no);
    float2 au = __bfloat1622float2(A[uo]), bu = __bfloat1622float2(B[uo]),
           cu = __bfloat1622float2(C[uo]);
    float2 ap = __bfloat1622float2(A[po]), bp = __bfloat1622float2(B[po]),
           cp = __bfloat1622float2(C[po]);
    float2 an = __bfloat1622float2(A[no]), bn = __bfloat1622float2(B[no]),
           cn = __bfloat1622float2(C[no]);

    float ux = eu.x + au.x + bu.x + cu.x, uy = eu.y + au.y + bu.y + cu.y;
    float px = ep.x + ap.x + bp.x + cp.x, py = ep.y + ap.y + bp.y + cp.y;
    float nx = en.x + an.x + bn.x + cn.x, ny = en.y + an.y + bn.y + cn.y;

    float pd = ux * px + uy * py;
    float nd = ux * nx + uy * ny;
    float sq = eu.x * eu.x + eu.y * eu.y
             + ep.x * ep.x + ep.y * ep.y
             + en.x * en.x + en.y * en.y;

#pragma unroll
    for (int o = 16; o; o >>= 1) {
        pd += __shfl_xor_sync(0xffffffffu, pd, o);
        nd += __shfl_xor_sync(0xffffffffu, nd, o);
        sq += __shfl_xor_sync(0xffffffffu, sq, o);
    }
    if (lane == 0) {
        float z = (nd - pd) * 0.0625f;                       // /16 for mean^2
        float sp = fmaxf(z, 0.f) + log1pf(expf(-fabsf(z)));  // softplus(neg-pos)
        atomicAdd(out, (sp + 5e-5f * sq) * (1.0f / BATCH));  // + L2_REG*0.5/BATCH
    }
}

extern "C" void kernel_launch(void* const* d_in, const int* in_sizes, int n_in,
                              void* d_out, int out_size) {
    const float* emb  = (const float*)d_in[0];
    const int*   edge = (const int*)d_in[1];
    const int*   src  = edge;
    const int*   dst  = edge + N_EDGES;
    const int*   user = (const int*)d_in[2];
    const int*   pos  = (const int*)d_in[3];
    const int*   neg  = (const int*)d_in[4];
    float*       out  = (float*)d_out;

    static cudaStream_t s1 = nullptr, s2 = nullptr, s3 = nullptr;
    static cudaEvent_t evInit, evA, evB, evZ, evP1, evConv;
    if (!s1) {
        cudaStreamCreateWithFlags(&s1, cudaStreamNonBlocking);
        cudaStreamCreateWithFlags(&s2, cudaStreamNonBlocking);
        cudaStreamCreateWithFlags(&s3, cudaStreamNonBlocking);
        cudaEventCreateWithFlags(&evInit, cudaEventDisableTiming);
        cudaEventCreateWithFlags(&evA,    cudaEventDisableTiming);
        cudaEventCreateWithFlags(&evB,    cudaEventDisableTiming);
        cudaEventCreateWithFlags(&evZ,    cudaEventDisableTiming);
        cudaEventCreateWithFlags(&evP1,   cudaEventDisableTiming);
        cudaEventCreateWithFlags(&evConv, cudaEventDisableTiming);
    }

    const int T = 256;
    const int G_NODES = (N_NODES + T - 1) / T;
    const int G_CMP   = (N_EDGES / 8 + T - 1) / T;
    const int G_MARK  = (9 * BATCH + T - 1) / T;
    const int G_CONV  = (N_NODES * (DIM / 8) + T - 1) / T;
    const int G_PROP  = 2048;
    const int G_ZERO  = 1024;

    // origin stream: serial critical chain (init -> mark -> compacts)
    k_init<<<G_NODES, T>>>();
    cudaEventRecord(evInit, 0);
    k_mark_batch<<<G_MARK, T>>>(user, pos, neg, out);
    // compactA also accumulates degree (fused former k_deg)
    k_compact8s<<<G_CMP, T>>>(src, dst, 2, -1, 1, 1, 1); // list2; mark fb1 (+nl1); deg
    cudaEventRecord(evA, 0);
    k_compact8s<<<G_CMP, T>>>(src, dst, 1, -1, 0, 1, 0); // list1; mark fb0 (+nl0)
    cudaEventRecord(evB, 0);
    // compactC overlapped with prop1a on s1: only f0 && !f1 edges
    k_compact8s<<<G_CMP, T>>>(src, dst, 0, 1, 0, 0, 0);  // -> list0

    // s3: emb -> bf16 conversion (independent)
    cudaStreamWaitEvent(s3, evInit, 0);
    k_conv<<<G_CONV, T, 0, s3>>>(emb);
    cudaEventRecord(evConv, s3);

    // s1: dinv after compactA's fused degree accumulation
    cudaStreamWaitEvent(s1, evA, 0);
    k_dinv<<<G_NODES, T, 0, s1>>>();

    // s2: single zero pass once ALL node lists are final (evB)
    cudaStreamWaitEvent(s2, evB, 0);
    k_zero_all<<<G_ZERO, T, 0, s2>>>();
    cudaEventRecord(evZ, s2);

    // prop1a on s1: EB -> XA over list1 edges, overlapped with compactC
    cudaStreamWaitEvent(s1, evZ, 0);
    cudaStreamWaitEvent(s1, evConv, 0);
    k_prop_list<<<G_PROP, T, 0, s1>>>(0, 1, 1);
    cudaEventRecord(evP1, s1);

    // join onto origin (evP1 transitively implies dinv + evZ + evConv)
    cudaStreamWaitEvent(0, evZ, 0);
    cudaStreamWaitEvent(0, evP1, 0);

    // prop1b: remaining layer-1 edges (f0 && !f1) -> XA
    k_prop_list<<<G_PROP, T>>>(0, 1, 0);
    // layers 2/3
    k_prop_list<<<G_PROP, T>>>(1, 2, 1);            // XA -> XB over list1
    k_prop_list<<<G_PROP, T>>>(2, 3, 2);            // XB -> XC over list2

    // fused loss (out zeroed in k_mark_batch)
    k_loss<<<BATCH / 8, T>>>(emb, user, pos, neg, out);
}

// round 15
// speedup vs baseline: 1.1316x; 1.1316x over previous
#include <cuda_runtime.h>
#include <cuda_bf16.h>
#include <cstdint>
#include <cstddef>

#define N_USERS   100000
#define N_NODES   500000
#define DIM       64
#define N_EDGES   2000000
#define BATCH     4096
#define NWORDS    ((N_NODES + 31) / 32)

// -------- device scratch (static, allocation-free) --------
// NOTE: never touch these symbols from host code (GB300 ATS would silently
// route through the host shadow at 200GB/s). All access via device selectors.
// ZERO-RESTORE INVARIANT: CUDA zero-initializes __device__ globals at module
// load. g_deg is re-zeroed by k_dinv after use; g_fb/g_ncnt/g_ecnt are
// re-zeroed by k_loss at the end of every call. So every kernel_launch starts
// from a zeroed state with NO init kernel.
__device__ __nv_bfloat16 g_XA[(size_t)N_NODES * DIM];  // bf16 layer buffers
__device__ __nv_bfloat16 g_XB[(size_t)N_NODES * DIM];
__device__ __nv_bfloat16 g_XC[(size_t)N_NODES * DIM];
__device__ float    g_dinv[N_NODES];
__device__ unsigned g_deg[N_NODES];
__device__ unsigned g_fb[3][NWORDS];       // needed-node bitmasks (L2-resident)
__device__ int      g_nl[3][N_NODES];      // compact node lists
__device__ int      g_ncnt[3];
__device__ int2     g_le[3][N_EDGES];      // compact edge lists (src,dst)
__device__ int      g_ecnt[3];

__device__ __forceinline__ __nv_bfloat16* xbuf(int sel) {
    return sel == 1 ? g_XA : (sel == 2 ? g_XB : g_XC);
}

// dinv = rsqrt(deg); also RESTORES deg to 0 for the next invocation
__global__ void k_dinv() {
    int i = blockIdx.x * blockDim.x + threadIdx.x;
    if (i < N_NODES) {
        unsigned d = g_deg[i];
        g_dinv[i] = d ? rsqrtf((float)d) : 0.0f;
        g_deg[i] = 0u;
    }
}

// warp-aggregated single-item append
__device__ __forceinline__ int wagg_append(int* counter, bool pred) {
    unsigned mask = __ballot_sync(0xffffffffu, pred);
    if (!pred) return -1;
    int lane   = threadIdx.x & 31;
    int leader = __ffs(mask) - 1;
    int rank   = __popc(mask & ((1u << lane) - 1));
    int base = 0;
    if (lane == leader) base = atomicAdd(counter, __popc(mask));
    base = __shfl_sync(mask, base, leader);
    return base + rank;
}

// warp-scan multi-append: ONE atomic per warp; all lanes participate
__device__ __forceinline__ int wscan_append(int* counter, int cnt) {
    int lane = threadIdx.x & 31;
    int incl = cnt;
#pragma unroll
    for (int o = 1; o < 32; o <<= 1) {
        int v = __shfl_up_sync(0xffffffffu, incl, o);
        if (lane >= o) incl += v;
    }
    int total = __shfl_sync(0xffffffffu, incl, 31);
    int base = 0;
    if (lane == 31 && total) base = atomicAdd(counter, total);
    base = __shfl_sync(0xffffffffu, base, 31);
    return base + incl - cnt;
}

__device__ __forceinline__ bool mark_node(int L, int idx) {
    unsigned bit = 1u << (idx & 31);
    unsigned old = atomicOr(&g_fb[L][idx >> 5], bit);
    return (old & bit) == 0u;
}

__device__ __forceinline__ bool test_node(int L, int idx) {
    return (g_fb[L][idx >> 5] >> (idx & 31)) & 1u;
}

// mark batch nodes in all 3 bitmasks + node lists; also zero the output scalar
__global__ void k_mark_batch(const int* __restrict__ u,
                             const int* __restrict__ p,
                             const int* __restrict__ n,
                             float* __restrict__ out) {
    int t = blockIdx.x * blockDim.x + threadIdx.x;
    if (t == 0) out[0] = 0.0f;
    bool act = (t < 9 * BATCH);
    int L = 0, idx = 0;
    if (act) {
        L = t / (3 * BATCH);
        int r = t - L * (3 * BATCH);
        idx = (r < BATCH) ? u[r]
            : (r < 2 * BATCH) ? p[r - BATCH]
                              : n[r - 2 * BATCH];
        act = mark_node(L, idx);
    }
#pragma unroll
    for (int LL = 0; LL < 3; LL++) {
        bool pred = act && (L == LL);
        int slot = wagg_append(&g_ncnt[LL], pred);
        if (pred) g_nl[LL][slot] = idx;
    }
}

// compaction, 8 edges/thread, warp-scan appends.
// pass: f[gate][dst] && (excl < 0 || !f[excl][dst]); optionally mark prev.
// do_deg: also accumulate in-degree for all 8 dsts (fused degree kernel).
__global__ void k_compact8s(const int* __restrict__ src, const int* __restrict__ dst,
                            int gate, int excl, int prev, int has_prev, int do_deg) {
    int t = blockIdx.x * blockDim.x + threadIdx.x;
    bool inb = (t < N_EDGES / 8);
    int4 dA = make_int4(0,0,0,0), dB = make_int4(0,0,0,0);
    if (inb) {
        dA = __ldg((const int4*)dst + 2 * t);
        dB = __ldg((const int4*)dst + 2 * t + 1);
    }
    int dd[8] = {dA.x, dA.y, dA.z, dA.w, dB.x, dB.y, dB.z, dB.w};

    if (do_deg && inb) {
#pragma unroll
        for (int i = 0; i < 8; i++)
            atomicAdd(&g_deg[dd[i]], 1u);
    }

    bool p[8];
    int cnt = 0;
#pragma unroll
    for (int i = 0; i < 8; i++) {
        p[i] = inb && test_node(gate, dd[i]);
        if (excl >= 0 && p[i]) p[i] = !test_node(excl, dd[i]);
        cnt += p[i];
    }
    int4 sA = make_int4(0,0,0,0), sB = make_int4(0,0,0,0);
    if (cnt) {
        sA = __ldg((const int4*)src + 2 * t);
        sB = __ldg((const int4*)src + 2 * t + 1);
    }
    int ss[8] = {sA.x, sA.y, sA.z, sA.w, sB.x, sB.y, sB.z, sB.w};

    int off = wscan_append(&g_ecnt[gate], cnt);
#pragma unroll
    for (int i = 0; i < 8; i++)
        if (p[i]) g_le[gate][off++] = make_int2(ss[i], dd[i]);

    if (has_prev) {
        bool nw[8];
        int ncnt = 0;
#pragma unroll
        for (int i = 0; i < 8; i++) {
            nw[i] = p[i] && mark_node(prev, ss[i]);
            ncnt += nw[i];
        }
        int noff = wscan_append(&g_ncnt[prev], ncnt);
#pragma unroll
        for (int i = 0; i < 8; i++)
            if (nw[i]) g_nl[prev][noff++] = ss[i];
    }
}

// zero all three bf16 buffers over their node lists in ONE kernel.
__global__ void k_zero_all() {
    int n0 = g_ncnt[0] * 8, n1 = g_ncnt[1] * 8, n2 = g_ncnt[2] * 8;
    int ntot = n0 + n1 + n2;
    int stride = gridDim.x * blockDim.x;
    for (int t = blockIdx.x * blockDim.x + threadIdx.x; t < ntot; t += stride) {
        uint4* y;
        int r, c;
        if (t < n0)            { y = (uint4*)g_XA; r = g_nl[0][t >> 3];  c = t & 7; }
        else if (t < n0 + n1)  { int q = t - n0;
                                 y = (uint4*)g_XB; r = g_nl[1][q >> 3];  c = q & 7; }
        else                   { int q = t - n0 - n1;
                                 y = (uint4*)g_XC; r = g_nl[2][q >> 3];  c = q & 7; }
        y[(size_t)r * 8 + c] = make_uint4(0u, 0u, 0u, 0u);
    }
}

// propagation over compact edge list: 8 lanes/edge, grid-stride.
// xsel==0: gather fp32 emb directly (32B/lane), convert inline; else bf16.
__global__ void k_prop_list(const float* __restrict__ emb,
                            int xsel, int ysel, int lsel) {
    int m = g_ecnt[lsel] * 8;
    uint4* y = (uint4*)xbuf(ysel);
    int stride = gridDim.x * blockDim.x;
    for (int t = blockIdx.x * blockDim.x + threadIdx.x; t < m; t += stride) {
        int e = t >> 3, lane = t & 7;
        int2  sd = __ldg(&g_le[lsel][e]);
        float w = __ldg(g_dinv + sd.x) * __ldg(g_dinv + sd.y);
        __nv_bfloat162 q0, q1, q2, q3;
        if (xsel == 0) {
            const float4* xf = (const float4*)emb + (size_t)sd.x * 16 + lane * 2;
            float4 a = __ldg(xf);
            float4 b = __ldg(xf + 1);
            q0 = __float22bfloat162_rn(make_float2(a.x * w, a.y * w));
            q1 = __float22bfloat162_rn(make_float2(a.z * w, a.w * w));
            q2 = __float22bfloat162_rn(make_float2(b.x * w, b.y * w));
            q3 = __float22bfloat162_rn(make_float2(b.z * w, b.w * w));
        } else {
            const uint4* x = (const uint4*)xbuf(xsel);
            uint4 v = __ldg(x + (size_t)sd.x * 8 + lane);
            __nv_bfloat162 w2 = __float2bfloat162_rn(w);
            q0 = __hmul2(*(__nv_bfloat162*)&v.x, w2);
            q1 = __hmul2(*(__nv_bfloat162*)&v.y, w2);
            q2 = __hmul2(*(__nv_bfloat162*)&v.z, w2);
            q3 = __hmul2(*(__nv_bfloat162*)&v.w, w2);
        }
        uint4* a = y + (size_t)sd.y * 8 + lane;
        asm volatile("red.global.add.noftz.v4.bf16x2 [%0], {%1, %2, %3, %4};"
                     :: "l"(a), "r"(*(unsigned*)&q0), "r"(*(unsigned*)&q1),
                        "r"(*(unsigned*)&q2), "r"(*(unsigned*)&q3)
                     : "memory");
    }
}

// -------- fused final loss + state restore --------
// one warp per batch element; trailing threads restore fb/counters to zero
__global__ void k_loss(const float* __restrict__ emb,
                       const int* __restrict__ user,
                       const int* __restrict__ pos,
                       const int* __restrict__ neg,
                       float* __restrict__ out) {
    int gt = blockIdx.x * blockDim.x + threadIdx.x;

    // restore zero-state for the next invocation (fb + counters)
    if (gt < NWORDS) { g_fb[0][gt] = 0u; g_fb[1][gt] = 0u; g_fb[2][gt] = 0u; }
    if (gt < 3) { g_ncnt[gt] = 0; g_ecnt[gt] = 0; }

    int w = gt >> 5;
    int lane = threadIdx.x & 31;
    if (w >= BATCH) return;

    int ui = user[w], pi = pos[w], ni = neg[w];

    const float2* E = (const float2*)emb;
    const __nv_bfloat162* A = (const __nv_bfloat162*)g_XA;
    const __nv_bfloat162* B = (const __nv_bfloat162*)g_XB;
    const __nv_bfloat162* C = (const __nv_bfloat162*)g_XC;

    size_t uo = (size_t)ui * 32 + lane;
    size_t po = (size_t)pi * 32 + lane;
    size_t no = (size_t)ni * 32 + lane;

    float2 eu = __ldg(E + uo), ep = __ldg(E + po), en = __ldg(E + no);
    float2 au = __bfloat1622float2(A[uo]), bu = __bfloat1622float2(B[uo]),
           cu = __bfloat1622float2(C[uo]);
    float2 ap = __bfloat1622float2(A[po]), bp = __bfloat1622float2(B[po]),
           cp = __bfloat1622float2(C[po]);
    float2 an = __bfloat1622float2(A[no]), bn = __bfloat1622float2(B[no]),
           cn = __bfloat1622float2(C[no]);

    float ux = eu.x + au.x + bu.x + cu.x, uy = eu.y + au.y + bu.y + cu.y;
    float px = ep.x + ap.x + bp.x + cp.x, py = ep.y + ap.y + bp.y + cp.y;
    float nx = en.x + an.x + bn.x + cn.x, ny = en.y + an.y + bn.y + cn.y;

    float pd = ux * px + uy * py;
    float nd = ux * nx + uy * ny;
    float sq = eu.x * eu.x + eu.y * eu.y
             + ep.x * ep.x + ep.y * ep.y
             + en.x * en.x + en.y * en.y;

#pragma unroll
    for (int o = 16; o; o >>= 1) {
        pd += __shfl_xor_sync(0xffffffffu, pd, o);
        nd += __shfl_xor_sync(0xffffffffu, nd, o);
        sq += __shfl_xor_sync(0xffffffffu, sq, o);
    }
    if (lane == 0) {
        float z = (nd - pd) * 0.0625f;                       // /16 for mean^2
        float sp = fmaxf(z, 0.f) + log1pf(expf(-fabsf(z)));  // softplus(neg-pos)
        atomicAdd(out, (sp + 5e-5f * sq) * (1.0f / BATCH));  // + L2_REG*0.5/BATCH
    }
}

extern "C" void kernel_launch(void* const* d_in, const int* in_sizes, int n_in,
                              void* d_out, int out_size) {
    const float* emb  = (const float*)d_in[0];
    const int*   edge = (const int*)d_in[1];
    const int*   src  = edge;
    const int*   dst  = edge + N_EDGES;
    const int*   user = (const int*)d_in[2];
    const int*   pos  = (const int*)d_in[3];
    const int*   neg  = (const int*)d_in[4];
    float*       out  = (float*)d_out;

    static cudaStream_t s1 = nullptr, s2 = nullptr;
    static cudaEvent_t evA, evB, evZ, evP1;
    if (!s1) {
        cudaStreamCreateWithFlags(&s1, cudaStreamNonBlocking);
        cudaStreamCreateWithFlags(&s2, cudaStreamNonBlocking);
        cudaEventCreateWithFlags(&evA,  cudaEventDisableTiming);
        cudaEventCreateWithFlags(&evB,  cudaEventDisableTiming);
        cudaEventCreateWithFlags(&evZ,  cudaEventDisableTiming);
        cudaEventCreateWithFlags(&evP1, cudaEventDisableTiming);
    }

    const int T = 256;
    const int G_NODES = (N_NODES + T - 1) / T;
    const int G_CMP   = (N_EDGES / 8 + T - 1) / T;
    const int G_MARK  = (9 * BATCH + T - 1) / T;
    const int G_PROP  = 2048;
    const int G_ZERO  = 1024;
    const int G_LOSS  = (BATCH * 32 + T - 1) / T;   // 512 blocks; covers NWORDS too

    // origin stream: serial critical chain (mark -> compacts); no init kernel —
    // state is zeroed at load and restored by k_dinv/k_loss each call.
    k_mark_batch<<<G_MARK, T>>>(user, pos, neg, out);
    // compactA also accumulates degree
    k_compact8s<<<G_CMP, T>>>(src, dst, 2, -1, 1, 1, 1); // list2; mark fb1 (+nl1); deg
    cudaEventRecord(evA, 0);
    k_compact8s<<<G_CMP, T>>>(src, dst, 1, -1, 0, 1, 0); // list1; mark fb0 (+nl0)
    cudaEventRecord(evB, 0);
    // compactC overlapped with prop1a on s1: only f0 && !f1 edges
    k_compact8s<<<G_CMP, T>>>(src, dst, 0, 1, 0, 0, 0);  // -> list0

    // s1: dinv after compactA's degree accumulation (also restores deg=0)
    cudaStreamWaitEvent(s1, evA, 0);
    k_dinv<<<G_NODES, T, 0, s1>>>();

    // s2: single zero pass once ALL node lists are final (evB)
    cudaStreamWaitEvent(s2, evB, 0);
    k_zero_all<<<G_ZERO, T, 0, s2>>>();
    cudaEventRecord(evZ, s2);

    // prop1a on s1: fp32 emb -> XA over list1 edges, overlapped with compactC
    cudaStreamWaitEvent(s1, evZ, 0);
    k_prop_list<<<G_PROP, T, 0, s1>>>(emb, 0, 1, 1);
    cudaEventRecord(evP1, s1);

    // join onto origin
    cudaStreamWaitEvent(0, evZ, 0);
    cudaStreamWaitEvent(0, evP1, 0);

    // prop1b: remaining layer-1 edges (f0 && !f1) -> XA, fp32 gather
    k_prop_list<<<G_PROP, T>>>(emb, 0, 1, 0);
    // layers 2/3 (bf16 gather)
    k_prop_list<<<G_PROP, T>>>(emb, 1, 2, 1);       // XA -> XB over list1
    k_prop_list<<<G_PROP, T>>>(emb, 2, 3, 2);       // XB -> XC over list2

    // fused loss + zero-state restore
    k_loss<<<G_LOSS, T>>>(emb, user, pos, neg, out);
}